// round 12
// baseline (speedup 1.0000x reference)
#include <cuda_runtime.h>

// Apply 2x2 complex gate (rows r0, r1 as (re0,im0,re1,im1)) to REAL 2-vec (c,s).
__device__ __forceinline__ float4 mat_real(float4 r0, float4 r1, float c, float s) {
    return make_float4(r0.x * c + r0.z * s, r0.y * c + r0.w * s,
                       r1.x * c + r1.z * s, r1.y * c + r1.w * s);
}
// Same for complex 2-vec v = (v0r,v0i,v1r,v1i).
__device__ __forceinline__ float4 mat_cpx(float4 r0, float4 r1, float4 v) {
    return make_float4(r0.x * v.x - r0.y * v.y + r0.z * v.z - r0.w * v.w,
                       r0.x * v.y + r0.y * v.x + r0.z * v.w + r0.w * v.z,
                       r1.x * v.x - r1.y * v.y + r1.z * v.z - r1.w * v.w,
                       r1.x * v.y + r1.y * v.x + r1.z * v.w + r1.w * v.z);
}
__device__ __forceinline__ float dz(float4 v) {        // |w0|^2 - |w1|^2
    return v.x * v.x + v.y * v.y - v.z * v.z - v.w * v.w;
}
__device__ __forceinline__ float p1_real(float4 r1, float c, float s) {
    float tr = r1.x * c + r1.z * s, ti = r1.y * c + r1.w * s;
    return tr * tr + ti * ti;
}

// Classical-branching evaluation in the D=diag(1,i) basis (initial per-qubit
// vector REAL: (sin pi p, -cos pi p); fused pair gate U' = G(tx)*diag(e^-ia,e^ia)).
// Block = TWO output rows of one image: 240 sims, 256 threads, 120 blocks total
// -> exactly one wave on 148 SMs.
__global__ void __launch_bounds__(256)
quanv_kernel(const float* __restrict__ x, const float* __restrict__ qp,
             float* __restrict__ out) {
    __shared__ float4 sU[4][16];   // fused gates [ch][2k]=row0, [ch][2k+1]=row1
    __shared__ float2 sT[4][30];   // pixel trig rows (2rb-1 .. 2rb+2), clamped

    int tid = threadIdx.x;
    int blk = blockIdx.x;          // = b*15 + rb ; rows h = 2rb, 2rb+1
    int rb = blk % 15, b = blk / 15;
    int h0 = 2 * rb;

    // Phase 1a: pixel trig (threads 0..119), rows pr = 2rb-1+rr clamped
    if (tid < 120) {
        int rr = tid / 30, cc = tid % 30;
        int pr = h0 - 1 + rr;
        pr = max(0, min(29, pr));
        const float* px = x + ((b * 30 + pr) * 30 + cc) * 3;
        float p = (px[0] + px[1] + px[2]) * (1.0f / 3.0f);
        float s, c;
        sincospif(p, &s, &c);
        sT[rr][cc] = make_float2(s, -c);
    }
    // Phase 1b: gate table (threads 128..159, one (ch,k) each)
    if (tid >= 128 && tid < 160) {
        int u = tid - 128, ch = u >> 3, k = u & 7;
        float tz = qp[ch * 16 + 2 * k], tx = qp[ch * 16 + 2 * k + 1];
        float sa, ca, sx, cx;
        sincosf(0.5f * tz, &sa, &ca);
        sincosf(0.5f * tx, &sx, &cx);
        sU[ch][2 * k]     = make_float4(cx * ca, -cx * sa, -sx * ca, -sx * sa);
        sU[ch][2 * k + 1] = make_float4(sx * ca, -sx * sa,  cx * ca,  cx * sa);
    }
    __syncthreads();

    if (tid >= 240) return;
    int hh = tid / 120, lane = tid % 120;     // hh: which of the two rows
    int ch = lane & 3, w = lane >> 2;
    int h = h0 + hh;
    int oidx = ((b * 30 + h) * 30 + w) * 4 + ch;

    if (h == 0 || h == 29 || w == 0 || w == 29) {
        out[oidx] = 0.0f;
        return;
    }

    const float4* gu = sU[ch];
    // qubit q = dr*3+dc -> sT[hh+dr][w-1+dc]
    float2 q0 = sT[hh][w - 1],     q1 = sT[hh][w],     q2 = sT[hh][w + 1];
    float2 q3 = sT[hh + 1][w - 1], q4 = sT[hh + 1][w], q5 = sT[hh + 1][w + 1];
    float2 q6 = sT[hh + 2][w - 1], q7 = sT[hh + 2][w], q8 = sT[hh + 2][w + 1];

    // ---------- B side: nB1 = P(q4 = 1) ----------
    float p8 = q8.y * q8.y;
    float t7 = p1_real(gu[7], q7.x, q7.y);            // U3 row1 (pair k=3)
    float P7 = (1.0f - p8) * (q7.y * q7.y) + p8 * t7;
    float t6 = p1_real(gu[11], q6.x, q6.y);           // U5 row1 (pair k=5)
    float P6 = (1.0f - P7) * (q6.y * q6.y) + P7 * t6;
    float p5 = q5.y * q5.y;

    float4 m10 = mat_real(gu[8], gu[9], q4.x, q4.y);  // U4 * v4 (pair k=4)
    float n00 = q4.y * q4.y;
    float n10 = m10.z * m10.z + m10.w * m10.w;
    float n01 = p1_real(gu[13], q4.x, q4.y);          // |row1(U6) v4|^2
    float4 r6 = gu[13];
    float tr = r6.x * m10.x - r6.y * m10.y + r6.z * m10.z - r6.w * m10.w;
    float ti = r6.x * m10.y + r6.y * m10.x + r6.z * m10.w + r6.w * m10.z;
    float n11 = tr * tr + ti * ti;
    float nB1 = (1.0f - p5) * ((1.0f - P6) * n00 + P6 * n01)
              + p5 * ((1.0f - P6) * n10 + P6 * n11);

    // ---------- A side: branch probs for q1, q2 ----------
    float p1p = q1.y * q1.y;
    float p3 = q3.y * q3.y;
    float t2 = p1_real(gu[3], q2.x, q2.y);            // U1 row1 (pair k=1)
    float P2 = (1.0f - p3) * (q2.y * q2.y) + p3 * t2;

    // ---------- q0 chain: U0^{b1}, U2^{b2}, U7^{b4} ----------
    float4 v10 = mat_real(gu[0], gu[1], q0.x, q0.y);
    float4 v01 = mat_real(gu[4], gu[5], q0.x, q0.y);
    float4 v11 = mat_cpx(gu[4], gu[5], v10);
    float4 w00 = mat_real(gu[14], gu[15], q0.x, q0.y);
    float4 w10 = mat_cpx(gu[14], gu[15], v10);
    float4 w01 = mat_cpx(gu[14], gu[15], v01);
    float4 w11 = mat_cpx(gu[14], gu[15], v11);

    float d00 = q0.x * q0.x - q0.y * q0.y;
    float nB0 = 1.0f - nB1;
    float e00 = nB0 * d00 + nB1 * dz(w00);
    float e10 = nB0 * dz(v10) + nB1 * dz(w10);
    float e01 = nB0 * dz(v01) + nB1 * dz(w01);
    float e11 = nB0 * dz(v11) + nB1 * dz(w11);

    float z = (1.0f - p1p) * ((1.0f - P2) * e00 + P2 * e01)
            + p1p * ((1.0f - P2) * e10 + P2 * e11);

    out[oidx] = 0.5f * (z + 1.0f);
}

extern "C" void kernel_launch(void* const* d_in, const int* in_sizes, int n_in,
                              void* d_out, int out_size) {
    const float* x = (const float*)d_in[0];       // (8,30,30,3) float32
    const float* qp = (const float*)d_in[1];      // (4,16) float32
    float* out = (float*)d_out;                   // (8,30,30,4) float32

    quanv_kernel<<<120, 256>>>(x, qp, out);       // 2 rows/block, single wave
}

// round 13
// speedup vs baseline: 1.0386x; 1.0386x over previous
#include <cuda_runtime.h>

// Apply 2x2 complex gate (rows r0, r1 as (re0,im0,re1,im1)) to REAL 2-vec (c,s).
__device__ __forceinline__ float4 mat_real(float4 r0, float4 r1, float c, float s) {
    return make_float4(r0.x * c + r0.z * s, r0.y * c + r0.w * s,
                       r1.x * c + r1.z * s, r1.y * c + r1.w * s);
}
// Same for complex 2-vec v = (v0r,v0i,v1r,v1i).
__device__ __forceinline__ float4 mat_cpx(float4 r0, float4 r1, float4 v) {
    return make_float4(r0.x * v.x - r0.y * v.y + r0.z * v.z - r0.w * v.w,
                       r0.x * v.y + r0.y * v.x + r0.z * v.w + r0.w * v.z,
                       r1.x * v.x - r1.y * v.y + r1.z * v.z - r1.w * v.w,
                       r1.x * v.y + r1.y * v.x + r1.z * v.w + r1.w * v.z);
}
__device__ __forceinline__ float dz(float4 v) {        // |w0|^2 - |w1|^2
    return v.x * v.x + v.y * v.y - v.z * v.z - v.w * v.w;
}
__device__ __forceinline__ float p1_real(float4 r1, float c, float s) {
    float tr = r1.x * c + r1.z * s, ti = r1.y * c + r1.w * s;
    return tr * tr + ti * ti;
}

// Classical-branching evaluation in the D=diag(1,i) basis (initial per-qubit
// vector REAL: (sin pi p, -cos pi p); fused pair gate U' = G(tx)*diag(e^-ia,e^ia)).
// Block = TWO output rows of one image: 240 sims, 256 threads, 120 blocks total
// -> single wave. Trig via MUFU intrinsics (accuracy budget: 1e-3 >> 1e-6).
__global__ void __launch_bounds__(256)
quanv_kernel(const float* __restrict__ x, const float* __restrict__ qp,
             float* __restrict__ out) {
    __shared__ float4 sU[4][16];   // fused gates [ch][2k]=row0, [ch][2k+1]=row1
    __shared__ float2 sT[4][30];   // pixel trig rows (2rb-1 .. 2rb+2), clamped

    int tid = threadIdx.x;
    int blk = blockIdx.x;          // = b*15 + rb ; rows h = 2rb, 2rb+1
    int rb = blk % 15, b = blk / 15;
    int h0 = 2 * rb;

    // Phase 1a: pixel trig (threads 0..119), rows pr = 2rb-1+rr clamped
    if (tid < 120) {
        int rr = tid / 30, cc = tid % 30;
        int pr = h0 - 1 + rr;
        pr = max(0, min(29, pr));
        const float* px = x + ((b * 30 + pr) * 30 + cc) * 3;
        float p = (px[0] + px[1] + px[2]) * (1.0f / 3.0f);
        float s, c;
        __sincosf(3.14159265358979f * p, &s, &c);   // MUFU fast path
        sT[rr][cc] = make_float2(s, -c);
    }
    // Phase 1b: gate table (threads 128..159, one (ch,k) each)
    if (tid >= 128 && tid < 160) {
        int u = tid - 128, ch = u >> 3, k = u & 7;
        float tz = qp[ch * 16 + 2 * k], tx = qp[ch * 16 + 2 * k + 1];
        float sa, ca, sx, cx;
        __sincosf(0.5f * tz, &sa, &ca);
        __sincosf(0.5f * tx, &sx, &cx);
        sU[ch][2 * k]     = make_float4(cx * ca, -cx * sa, -sx * ca, -sx * sa);
        sU[ch][2 * k + 1] = make_float4(sx * ca, -sx * sa,  cx * ca,  cx * sa);
    }
    __syncthreads();

    if (tid >= 240) return;
    int hh = tid >= 120;                      // which of the two rows
    int lane = tid - 120 * hh;
    int ch = lane & 3, w = lane >> 2;
    int h = h0 + hh;
    int oidx = blk * 240 + tid;               // == ((b*30+h)*30+w)*4+ch

    if (h == 0 || h == 29 || w == 0 || w == 29) {
        out[oidx] = 0.0f;
        return;
    }

    const float4* gu = sU[ch];
    // qubit q = dr*3+dc -> sT[hh+dr][w-1+dc]
    float2 q0 = sT[hh][w - 1],     q1 = sT[hh][w],     q2 = sT[hh][w + 1];
    float2 q3 = sT[hh + 1][w - 1], q4 = sT[hh + 1][w], q5 = sT[hh + 1][w + 1];
    float2 q6 = sT[hh + 2][w - 1], q7 = sT[hh + 2][w], q8 = sT[hh + 2][w + 1];

    // ---------- B side: nB1 = P(q4 = 1) ----------
    float p8 = q8.y * q8.y;
    float t7 = p1_real(gu[7], q7.x, q7.y);            // U3 row1 (pair k=3)
    float P7 = (1.0f - p8) * (q7.y * q7.y) + p8 * t7;
    float t6 = p1_real(gu[11], q6.x, q6.y);           // U5 row1 (pair k=5)
    float P6 = (1.0f - P7) * (q6.y * q6.y) + P7 * t6;
    float p5 = q5.y * q5.y;

    float4 m10 = mat_real(gu[8], gu[9], q4.x, q4.y);  // U4 * v4 (pair k=4)
    float n00 = q4.y * q4.y;
    float n10 = m10.z * m10.z + m10.w * m10.w;
    float n01 = p1_real(gu[13], q4.x, q4.y);          // |row1(U6) v4|^2
    float4 r6 = gu[13];
    float tr = r6.x * m10.x - r6.y * m10.y + r6.z * m10.z - r6.w * m10.w;
    float ti = r6.x * m10.y + r6.y * m10.x + r6.z * m10.w + r6.w * m10.z;
    float n11 = tr * tr + ti * ti;
    float nB1 = (1.0f - p5) * ((1.0f - P6) * n00 + P6 * n01)
              + p5 * ((1.0f - P6) * n10 + P6 * n11);

    // ---------- A side: branch probs for q1, q2 ----------
    float p1p = q1.y * q1.y;
    float p3 = q3.y * q3.y;
    float t2 = p1_real(gu[3], q2.x, q2.y);            // U1 row1 (pair k=1)
    float P2 = (1.0f - p3) * (q2.y * q2.y) + p3 * t2;

    // ---------- q0 chain: U0^{b1}, U2^{b2}, U7^{b4} ----------
    float4 v10 = mat_real(gu[0], gu[1], q0.x, q0.y);
    float4 v01 = mat_real(gu[4], gu[5], q0.x, q0.y);
    float4 v11 = mat_cpx(gu[4], gu[5], v10);
    float4 w00 = mat_real(gu[14], gu[15], q0.x, q0.y);
    float4 w10 = mat_cpx(gu[14], gu[15], v10);
    float4 w01 = mat_cpx(gu[14], gu[15], v01);
    float4 w11 = mat_cpx(gu[14], gu[15], v11);

    float d00 = q0.x * q0.x - q0.y * q0.y;
    float nB0 = 1.0f - nB1;
    float e00 = nB0 * d00 + nB1 * dz(w00);
    float e10 = nB0 * dz(v10) + nB1 * dz(w10);
    float e01 = nB0 * dz(v01) + nB1 * dz(w01);
    float e11 = nB0 * dz(v11) + nB1 * dz(w11);

    float z = (1.0f - p1p) * ((1.0f - P2) * e00 + P2 * e01)
            + p1p * ((1.0f - P2) * e10 + P2 * e11);

    out[oidx] = 0.5f * (z + 1.0f);
}

extern "C" void kernel_launch(void* const* d_in, const int* in_sizes, int n_in,
                              void* d_out, int out_size) {
    const float* x = (const float*)d_in[0];       // (8,30,30,3) float32
    const float* qp = (const float*)d_in[1];      // (4,16) float32
    float* out = (float*)d_out;                   // (8,30,30,4) float32

    quanv_kernel<<<120, 256>>>(x, qp, out);       // 2 rows/block, single wave
}